// round 1
// baseline (speedup 1.0000x reference)
#include <cuda_runtime.h>
#include <math.h>

#define N_STREAMS 8192
#define HH 512
#define G3 1536
#define EE 128
#define VV 128
#define S_STEPS 32

// Persistent scratch (static __device__ arrays: allocation-free).
__device__ float g_gctx[N_STREAMS * G3];   // context part of gi, + b_ih   (48 MB)
__device__ float g_fcctx[N_STREAMS * VV];  // context part of fc, + fc_b   (4 MB)
__device__ float g_embgi[VV * G3];         // per-char gi contribution
__device__ float g_fcemb[VV * VV];         // per-char fc contribution
__device__ float g_h[N_STREAMS * HH];      // hidden state (in-place per step)
__device__ int   g_ch[N_STREAMS];          // current fed-back char

// ---------------------------------------------------------------------------
__global__ void init_kernel(const float* __restrict__ encoded,
                            const int* __restrict__ init_char) {
    int i = blockIdx.x * blockDim.x + threadIdx.x;
    if (i < N_STREAMS * HH / 4)
        reinterpret_cast<float4*>(g_h)[i] =
            reinterpret_cast<const float4*>(encoded)[i];
    if (i < N_STREAMS) g_ch[i] = init_char[i];
}

// embgi[c][j] = emb_table[c] . W_ih[j][0:128]; fcemb[c][v] = emb_table[c] . fc_W[v][0:128]
__global__ __launch_bounds__(128)
void emb_kernel(const float* __restrict__ emb_table,
                const float* __restrict__ W_ih,
                const float* __restrict__ fc_W) {
    __shared__ float er[EE];
    int c = blockIdx.y;
    int tx = threadIdx.x;
    er[tx] = emb_table[c * EE + tx];
    __syncthreads();
    int col = blockIdx.x * 128 + tx;   // [0, 1664): 1536 gi cols + 128 fc cols
    const float* brow = (col < G3) ? (W_ih + (size_t)col * 640)
                                   : (fc_W + (size_t)(col - G3) * 1152);
    float acc = 0.f;
#pragma unroll 8
    for (int e = 0; e < EE; e += 4) {
        float4 b = *reinterpret_cast<const float4*>(brow + e);
        acc += er[e] * b.x + er[e + 1] * b.y + er[e + 2] * b.z + er[e + 3] * b.w;
    }
    if (col < G3) g_embgi[c * G3 + col] = acc;
    else          g_fcemb[c * VV + (col - G3)] = acc;
}

// gctx[n][j] = b_ih[j] + ctx[n] . W_ih[j][128:640]   (blockIdx.y < 12)
// fcctx[n][v] = fc_b[v] + ctx[n] . fc_W[v][128:640]  (blockIdx.y == 12)
__global__ __launch_bounds__(256)
void ctx_kernel(const float* __restrict__ enc, const float* __restrict__ W_ih,
                const float* __restrict__ b_ih, const float* __restrict__ fc_W,
                const float* __restrict__ fc_b) {
    extern __shared__ float sm[];
    float* As = sm;               // [512][32] transposed A tile
    float* Bs = sm + HH * 32;     // [16][128]
    int t = threadIdx.x, w = t >> 5, l = t & 31;
    int n0 = blockIdx.x * 32;
    int ct = blockIdx.y;          // 0..12
    {
        int s = t >> 3, kb = (t & 7) * 64;
        const float* ap = enc + (size_t)(n0 + s) * HH + kb;
#pragma unroll 4
        for (int k = 0; k < 64; k += 4) {
            float4 q = *reinterpret_cast<const float4*>(ap + k);
            As[(kb + k    ) * 32 + s] = q.x;
            As[(kb + k + 1) * 32 + s] = q.y;
            As[(kb + k + 2) * 32 + s] = q.z;
            As[(kb + k + 3) * 32 + s] = q.w;
        }
    }
    const float* Bbase; int ldb;
    if (ct < 12) { Bbase = W_ih + (size_t)ct * 128 * 640 + EE; ldb = 640; }
    else         { Bbase = fc_W + EE;                          ldb = 1152; }
    float acc[4][4];
#pragma unroll
    for (int i = 0; i < 4; i++) { acc[i][0] = acc[i][1] = acc[i][2] = acc[i][3] = 0.f; }
    int rl = l >> 2, kq = l & 3;
    for (int k0 = 0; k0 < HH; k0 += 16) {
        __syncthreads();
#pragma unroll
        for (int ii = 0; ii < 2; ++ii) {
            int c = ii * 64 + w * 8 + rl;
            float4 q = *reinterpret_cast<const float4*>(Bbase + (size_t)c * ldb + k0 + kq * 4);
            Bs[(kq * 4    ) * 128 + c] = q.x;
            Bs[(kq * 4 + 1) * 128 + c] = q.y;
            Bs[(kq * 4 + 2) * 128 + c] = q.z;
            Bs[(kq * 4 + 3) * 128 + c] = q.w;
        }
        __syncthreads();
#pragma unroll
        for (int kk = 0; kk < 16; ++kk) {
            float4 a = *reinterpret_cast<const float4*>(&As[(k0 + kk) * 32 + w * 4]);
            float4 b = *reinterpret_cast<const float4*>(&Bs[kk * 128 + l * 4]);
            float av[4] = {a.x, a.y, a.z, a.w};
            float bv[4] = {b.x, b.y, b.z, b.w};
#pragma unroll
            for (int si = 0; si < 4; ++si)
#pragma unroll
                for (int j = 0; j < 4; ++j) acc[si][j] += av[si] * bv[j];
        }
    }
    const float* bias = (ct < 12) ? (b_ih + ct * 128) : fc_b;
    float4 bb = *reinterpret_cast<const float4*>(bias + l * 4);
    float bvv[4] = {bb.x, bb.y, bb.z, bb.w};
#pragma unroll
    for (int si = 0; si < 4; ++si) {
        int n = n0 + w * 4 + si;
        float4 r;
        r.x = acc[si][0] + bvv[0]; r.y = acc[si][1] + bvv[1];
        r.z = acc[si][2] + bvv[2]; r.w = acc[si][3] + bvv[3];
        if (ct < 12)
            *reinterpret_cast<float4*>(g_gctx + (size_t)n * G3 + ct * 128 + l * 4) = r;
        else
            *reinterpret_cast<float4*>(g_fcctx + (size_t)n * VV + l * 4) = r;
    }
}

// ---------------------------------------------------------------------------
// One decode step, fully fused: gh GEMM -> GRU gates -> fc GEMM -> argmax.
// Block = 32 streams (block-exclusive rows -> in-place h update is safe).
__global__ __launch_bounds__(256, 2)
void step_kernel(const float* __restrict__ W_hh, const float* __restrict__ b_hh,
                 const float* __restrict__ fc_W, float* __restrict__ out, int step) {
    extern __shared__ float sm[];
    float* hs = sm;                  // [512][32] old h, transposed
    float* Bs = sm + HH * 32;        // [16][384] weight staging (reused in phase 2)
    int* sch = reinterpret_cast<int*>(Bs + 16 * 384);   // [32] chars

    int t = threadIdx.x, w = t >> 5, l = t & 31;
    int n0 = blockIdx.x * 32;
    if (t < 32) sch[t] = g_ch[n0 + t];
    {
        int s = t >> 3, kb = (t & 7) * 64;
        const float* hp = g_h + (size_t)(n0 + s) * HH + kb;
#pragma unroll 4
        for (int k = 0; k < 64; k += 4) {
            float4 q = *reinterpret_cast<const float4*>(hp + k);
            hs[(kb + k    ) * 32 + s] = q.x;
            hs[(kb + k + 1) * 32 + s] = q.y;
            hs[(kb + k + 2) * 32 + s] = q.z;
            hs[(kb + k + 3) * 32 + s] = q.w;
        }
    }
    int rl = l >> 2, kq = l & 3;

    // ---- Phase 1: gh = h @ W_hh.T (+b_hh), gates, h_new (4 j-tiles of 128) ----
    for (int jt = 0; jt < 4; ++jt) {
        float acc[4][12];
#pragma unroll
        for (int i = 0; i < 4; i++)
#pragma unroll
            for (int j = 0; j < 12; j++) acc[i][j] = 0.f;

        for (int k0 = 0; k0 < HH; k0 += 16) {
            __syncthreads();
#pragma unroll
            for (int ii = 0; ii < 6; ++ii) {       // 384 rows: 3 gates x 128 j
                int c = ii * 64 + w * 8 + rl;
                int g = c >> 7, jj = c & 127;
                float4 q = *reinterpret_cast<const float4*>(
                    W_hh + (size_t)(g * HH + jt * 128 + jj) * HH + k0 + kq * 4);
                Bs[(kq * 4    ) * 384 + c] = q.x;
                Bs[(kq * 4 + 1) * 384 + c] = q.y;
                Bs[(kq * 4 + 2) * 384 + c] = q.z;
                Bs[(kq * 4 + 3) * 384 + c] = q.w;
            }
            __syncthreads();
#pragma unroll
            for (int kk = 0; kk < 16; ++kk) {
                float4 av4 = *reinterpret_cast<const float4*>(&hs[(k0 + kk) * 32 + w * 4]);
                float av[4] = {av4.x, av4.y, av4.z, av4.w};
                float4 b0 = *reinterpret_cast<const float4*>(&Bs[kk * 384 + l * 4]);
                float4 b1 = *reinterpret_cast<const float4*>(&Bs[kk * 384 + 128 + l * 4]);
                float4 b2 = *reinterpret_cast<const float4*>(&Bs[kk * 384 + 256 + l * 4]);
                float bv[12] = {b0.x, b0.y, b0.z, b0.w,
                                b1.x, b1.y, b1.z, b1.w,
                                b2.x, b2.y, b2.z, b2.w};
#pragma unroll
                for (int si = 0; si < 4; ++si)
#pragma unroll
                    for (int j = 0; j < 12; ++j) acc[si][j] += av[si] * bv[j];
            }
        }
        // gates for this j-tile
#pragma unroll
        for (int si = 0; si < 4; ++si) {
            int n = n0 + w * 4 + si;
            int cc = sch[w * 4 + si];
            int jb = jt * 128 + l * 4;
            const float* gp = g_gctx + (size_t)n * G3 + jb;
            const float* ep = g_embgi + (size_t)cc * G3 + jb;
            float4 gr = *reinterpret_cast<const float4*>(gp);
            float4 gz = *reinterpret_cast<const float4*>(gp + 512);
            float4 gn = *reinterpret_cast<const float4*>(gp + 1024);
            float4 er = *reinterpret_cast<const float4*>(ep);
            float4 ez = *reinterpret_cast<const float4*>(ep + 512);
            float4 en = *reinterpret_cast<const float4*>(ep + 1024);
            float4 br = *reinterpret_cast<const float4*>(b_hh + jb);
            float4 bz = *reinterpret_cast<const float4*>(b_hh + 512 + jb);
            float4 bn = *reinterpret_cast<const float4*>(b_hh + 1024 + jb);
            float fgr[4] = {gr.x, gr.y, gr.z, gr.w};
            float fgz[4] = {gz.x, gz.y, gz.z, gz.w};
            float fgn[4] = {gn.x, gn.y, gn.z, gn.w};
            float fer[4] = {er.x, er.y, er.z, er.w};
            float fez[4] = {ez.x, ez.y, ez.z, ez.w};
            float fen[4] = {en.x, en.y, en.z, en.w};
            float fbr[4] = {br.x, br.y, br.z, br.w};
            float fbz[4] = {bz.x, bz.y, bz.z, bz.w};
            float fbn[4] = {bn.x, bn.y, bn.z, bn.w};
            float hv[4];
#pragma unroll
            for (int j = 0; j < 4; ++j) {
                float pr = fgr[j] + fer[j] + acc[si][j]     + fbr[j];
                float pz = fgz[j] + fez[j] + acc[si][4 + j] + fbz[j];
                float hn = acc[si][8 + j] + fbn[j];                    // W_hn h + b_hn
                float r = 1.f / (1.f + expf(-pr));
                float z = 1.f / (1.f + expf(-pz));
                float nn = tanhf(fgn[j] + fen[j] + r * hn);
                float ho = hs[(jb + j) * 32 + w * 4 + si];
                hv[j] = (1.f - z) * nn + z * ho;
            }
            *reinterpret_cast<float4*>(g_h + (size_t)n * HH + jb) =
                make_float4(hv[0], hv[1], hv[2], hv[3]);
        }
    }

    // ---- Phase 2: pred = fc_ctx + fc_emb[ch] + h_new @ fc_W[:,640:].T ; argmax ----
    float acc2[4][4];
#pragma unroll
    for (int i = 0; i < 4; i++) { acc2[i][0] = acc2[i][1] = acc2[i][2] = acc2[i][3] = 0.f; }
    for (int k0 = 0; k0 < HH; k0 += 16) {
        __syncthreads();       // also orders phase-1 g_h writes before reads below
        {
            int v = t & 127, kh = (t >> 7) * 8;
            const float* src = fc_W + (size_t)v * 1152 + 640 + k0 + kh;
            float4 q0 = *reinterpret_cast<const float4*>(src);
            float4 q1 = *reinterpret_cast<const float4*>(src + 4);
            Bs[(kh    ) * 128 + v] = q0.x; Bs[(kh + 1) * 128 + v] = q0.y;
            Bs[(kh + 2) * 128 + v] = q0.z; Bs[(kh + 3) * 128 + v] = q0.w;
            Bs[(kh + 4) * 128 + v] = q1.x; Bs[(kh + 5) * 128 + v] = q1.y;
            Bs[(kh + 6) * 128 + v] = q1.z; Bs[(kh + 7) * 128 + v] = q1.w;
        }
        __syncthreads();
#pragma unroll 4
        for (int kk = 0; kk < 16; ++kk) {
            float a[4];
#pragma unroll
            for (int si = 0; si < 4; ++si)
                a[si] = g_h[(size_t)(n0 + w * 4 + si) * HH + k0 + kk];
            float4 b = *reinterpret_cast<const float4*>(&Bs[kk * 128 + l * 4]);
            float bv[4] = {b.x, b.y, b.z, b.w};
#pragma unroll
            for (int si = 0; si < 4; ++si)
#pragma unroll
                for (int j = 0; j < 4; ++j) acc2[si][j] += a[si] * bv[j];
        }
    }
#pragma unroll
    for (int si = 0; si < 4; ++si) {
        int n = n0 + w * 4 + si;
        int cc = sch[w * 4 + si];
        float4 fc4 = *reinterpret_cast<const float4*>(g_fcctx + (size_t)n * VV + l * 4);
        float4 fe4 = *reinterpret_cast<const float4*>(g_fcemb + (size_t)cc * VV + l * 4);
        float p[4] = {acc2[si][0] + fc4.x + fe4.x, acc2[si][1] + fc4.y + fe4.y,
                      acc2[si][2] + fc4.z + fe4.z, acc2[si][3] + fc4.w + fe4.w};
        *reinterpret_cast<float4*>(out + ((size_t)n * S_STEPS + step) * VV + l * 4) =
            make_float4(p[0], p[1], p[2], p[3]);
        // argmax over 128 logits, first-index tie-break (matches jnp.argmax)
        float bvv = p[0]; int bi = l * 4;
#pragma unroll
        for (int j = 1; j < 4; ++j) if (p[j] > bvv) { bvv = p[j]; bi = l * 4 + j; }
#pragma unroll
        for (int off = 16; off > 0; off >>= 1) {
            float ov = __shfl_xor_sync(0xffffffffu, bvv, off);
            int   oi = __shfl_xor_sync(0xffffffffu, bi, off);
            if (ov > bvv || (ov == bvv && oi < bi)) { bvv = ov; bi = oi; }
        }
        if (l == 0) g_ch[n] = bi;
    }
}

// ---------------------------------------------------------------------------
extern "C" void kernel_launch(void* const* d_in, const int* in_sizes, int n_in,
                              void* d_out, int out_size) {
    // Resolve inputs by element count (robust to how the scalar seq_len is passed).
    const float *encoded = 0, *emb_table = 0, *W_ih = 0, *W_hh = 0,
                *b_ih = 0, *b_hh = 0, *fc_W = 0, *fc_b = 0;
    const int* init_char = 0;
    for (int i = 0; i < n_in; ++i) {
        switch (in_sizes[i]) {
            case 8192 * 512:  encoded   = (const float*)d_in[i]; break;
            case 8192:        init_char = (const int*)d_in[i];   break;
            case 128 * 128:   emb_table = (const float*)d_in[i]; break;
            case 1536 * 640:  W_ih      = (const float*)d_in[i]; break;
            case 1536 * 512:  W_hh      = (const float*)d_in[i]; break;
            case 1536:        if (!b_ih) b_ih = (const float*)d_in[i];
                              else       b_hh = (const float*)d_in[i]; break;
            case 128 * 1152:  fc_W      = (const float*)d_in[i]; break;
            case 128:         fc_b      = (const float*)d_in[i]; break;
            default: break;   // seq_len scalar — S hardcoded to 32
        }
    }
    float* out = (float*)d_out;

    cudaFuncSetAttribute(ctx_kernel, cudaFuncAttributeMaxDynamicSharedMemorySize,
                         (HH * 32 + 16 * 128) * (int)sizeof(float));
    size_t smemStep = (HH * 32 + 16 * 384) * sizeof(float) + 32 * sizeof(int);
    cudaFuncSetAttribute(step_kernel, cudaFuncAttributeMaxDynamicSharedMemorySize,
                         (int)smemStep);

    init_kernel<<<(N_STREAMS * HH / 4 + 255) / 256, 256>>>(encoded, init_char);
    emb_kernel<<<dim3(13, 128), 128>>>(emb_table, W_ih, fc_W);
    ctx_kernel<<<dim3(256, 13), 256, (HH * 32 + 16 * 128) * sizeof(float)>>>(
        encoded, W_ih, b_ih, fc_W, fc_b);
    for (int s = 0; s < S_STEPS; ++s)
        step_kernel<<<256, 256, smemStep>>>(W_hh, b_hh, fc_W, out, s);
}

// round 4
// speedup vs baseline: 2.7490x; 2.7490x over previous
#include <cuda_runtime.h>
#include <cuda_bf16.h>
#include <math.h>
#include <stdint.h>

#define NS 8192
#define HHD 512
#define G3 1536
#define EE 128
#define VV 128
#define SSTEPS 32
#define NCTA 128
#define CROWS 64

// smem byte offsets
#define SM_A 0
#define A_SPLIT 66560          // 64*520*2 bytes per split
#define SM_B 133120
#define B_BUF 36864            // per buffer (2 splits)
#define B_SPL 18432            // 128*72*2
#define SM_BHN 206848          // 512 floats: b_hh n-gate part
#define SM_SCH 208896          // 64 ints
#define SM_ARGV 209152         // 256 floats
#define SM_ARGI 210176         // 256 ints
#define SMEM_TOT 211200

// ---------------- persistent device scratch ----------------
__device__ float g_gctx[(size_t)NS * G3];    // [n][1536], b_ih (+ b_hh for r,z) folded
__device__ float g_fcctx[(size_t)NS * VV];   // [n][128], fc_b folded
__device__ float g_embgi[VV * G3];           // [c][1536]
__device__ float g_fcemb[VV * VV];           // [c][128]
__device__ float g_h[(size_t)NS * HHD];      // h_new staging (fp32)
__device__ __align__(128) __nv_bfloat16 g_wpack[12 * 8 * 2 * 128 * 64];  // [tile][kc][split][n][k]
__device__ __align__(128) __nv_bfloat16 g_fcpack[8 * 2 * 128 * 64];      // [kc][split][v][k]

// ---------------- small helpers ----------------
__device__ __forceinline__ uint32_t smem_u32(const void* p) {
    uint32_t a;
    asm("{ .reg .u64 t; cvta.to.shared.u64 t, %1; cvt.u32.u64 %0, t; }" : "=r"(a) : "l"(p));
    return a;
}
__device__ __forceinline__ void ldsm4(uint32_t addr, uint32_t r[4]) {
    asm volatile("ldmatrix.sync.aligned.m8n8.x4.shared.b16 {%0,%1,%2,%3}, [%4];"
        : "=r"(r[0]), "=r"(r[1]), "=r"(r[2]), "=r"(r[3]) : "r"(addr));
}
__device__ __forceinline__ void mma16816(float* c, const uint32_t a[4], const uint32_t b[2]) {
    asm volatile("mma.sync.aligned.m16n8k16.row.col.f32.bf16.bf16.f32 "
        "{%0,%1,%2,%3}, {%4,%5,%6,%7}, {%8,%9}, {%0,%1,%2,%3};"
        : "+f"(c[0]), "+f"(c[1]), "+f"(c[2]), "+f"(c[3])
        : "r"(a[0]), "r"(a[1]), "r"(a[2]), "r"(a[3]), "r"(b[0]), "r"(b[1]));
}
__device__ __forceinline__ void cp16(uint32_t dst, const void* src) {
    asm volatile("cp.async.cg.shared.global [%0], [%1], 16;" :: "r"(dst), "l"(src));
}
__device__ __forceinline__ void bsplit(float v, unsigned short& h, unsigned short& l) {
    __nv_bfloat16 bh = __float2bfloat16(v);
    __nv_bfloat16 bl = __float2bfloat16(v - __bfloat162float(bh));
    h = __bfloat16_as_ushort(bh);
    l = __bfloat16_as_ushort(bl);
}

// ---------------- prep kernels ----------------
__global__ void pack_w_kernel(const float* __restrict__ W_hh) {
    int idx = blockIdx.x * 256 + threadIdx.x;
    if (idx >= G3 * HHD) return;
    int R = idx >> 9, C = idx & 511;
    int g = R >> 9, rem = R & 511, jt = rem >> 7, n = rem & 127;
    int kc = C >> 6, k = C & 63;
    int tile = jt * 3 + g;
    unsigned short h, l;
    bsplit(W_hh[idx], h, l);
    size_t base = ((size_t)(tile * 8 + kc) * 2) * 8192 + n * 64 + k;
    g_wpack[base] = __ushort_as_bfloat16(h);
    g_wpack[base + 8192] = __ushort_as_bfloat16(l);
}

__global__ void pack_fc_kernel(const float* __restrict__ fc_W) {
    int idx = blockIdx.x * 256 + threadIdx.x;
    if (idx >= VV * HHD) return;
    int v = idx >> 9, C = idx & 511;
    int kc = C >> 6, k = C & 63;
    unsigned short h, l;
    bsplit(fc_W[(size_t)v * 1152 + 640 + C], h, l);
    size_t base = ((size_t)kc * 2) * 8192 + v * 64 + k;
    g_fcpack[base] = __ushort_as_bfloat16(h);
    g_fcpack[base + 8192] = __ushort_as_bfloat16(l);
}

__global__ __launch_bounds__(128)
void emb_kernel(const float* __restrict__ emb_table,
                const float* __restrict__ W_ih,
                const float* __restrict__ fc_W) {
    __shared__ float er[EE];
    int c = blockIdx.y;
    int tx = threadIdx.x;
    er[tx] = emb_table[c * EE + tx];
    __syncthreads();
    int col = blockIdx.x * 128 + tx;   // [0, 1664)
    const float* brow = (col < G3) ? (W_ih + (size_t)col * 640)
                                   : (fc_W + (size_t)(col - G3) * 1152);
    float acc = 0.f;
#pragma unroll 8
    for (int e = 0; e < EE; e += 4) {
        float4 b = *reinterpret_cast<const float4*>(brow + e);
        acc += er[e] * b.x + er[e + 1] * b.y + er[e + 2] * b.z + er[e + 3] * b.w;
    }
    if (col < G3) g_embgi[c * G3 + col] = acc;
    else          g_fcemb[c * VV + (col - G3)] = acc;
}

__global__ __launch_bounds__(256)
void ctx_kernel(const float* __restrict__ enc, const float* __restrict__ W_ih,
                const float* __restrict__ b_ih, const float* __restrict__ b_hh,
                const float* __restrict__ fc_W, const float* __restrict__ fc_b) {
    extern __shared__ char smraw[];
    float* smf = reinterpret_cast<float*>(smraw);
    float* As = smf;               // [512][32] transposed A tile
    float* Bs = smf + HHD * 32;    // [16][128]
    int t = threadIdx.x, w = t >> 5, l = t & 31;
    int n0 = blockIdx.x * 32;
    int ct = blockIdx.y;          // 0..12
    {
        int s = t >> 3, kb = (t & 7) * 64;
        const float* ap = enc + (size_t)(n0 + s) * HHD + kb;
#pragma unroll 4
        for (int k = 0; k < 64; k += 4) {
            float4 q = *reinterpret_cast<const float4*>(ap + k);
            As[(kb + k) * 32 + s] = q.x;
            As[(kb + k + 1) * 32 + s] = q.y;
            As[(kb + k + 2) * 32 + s] = q.z;
            As[(kb + k + 3) * 32 + s] = q.w;
        }
    }
    const float* Bbase; int ldb;
    if (ct < 12) { Bbase = W_ih + (size_t)ct * 128 * 640 + EE; ldb = 640; }
    else         { Bbase = fc_W + EE;                          ldb = 1152; }
    float acc[4][4];
#pragma unroll
    for (int i = 0; i < 4; i++) { acc[i][0] = acc[i][1] = acc[i][2] = acc[i][3] = 0.f; }
    int rl = l >> 2, kq = l & 3;
    for (int k0 = 0; k0 < HHD; k0 += 16) {
        __syncthreads();
#pragma unroll
        for (int ii = 0; ii < 2; ++ii) {
            int c = ii * 64 + w * 8 + rl;
            float4 q = *reinterpret_cast<const float4*>(Bbase + (size_t)c * ldb + k0 + kq * 4);
            Bs[(kq * 4) * 128 + c] = q.x;
            Bs[(kq * 4 + 1) * 128 + c] = q.y;
            Bs[(kq * 4 + 2) * 128 + c] = q.z;
            Bs[(kq * 4 + 3) * 128 + c] = q.w;
        }
        __syncthreads();
#pragma unroll
        for (int kk = 0; kk < 16; ++kk) {
            float4 a = *reinterpret_cast<const float4*>(&As[(k0 + kk) * 32 + w * 4]);
            float4 b = *reinterpret_cast<const float4*>(&Bs[kk * 128 + l * 4]);
            float av[4] = {a.x, a.y, a.z, a.w};
            float bv[4] = {b.x, b.y, b.z, b.w};
#pragma unroll
            for (int si = 0; si < 4; ++si)
#pragma unroll
                for (int j = 0; j < 4; ++j) acc[si][j] += av[si] * bv[j];
        }
    }
    const float* bias = (ct < 12) ? (b_ih + ct * 128) : fc_b;
    float4 bb = *reinterpret_cast<const float4*>(bias + l * 4);
    float bvv[4] = {bb.x, bb.y, bb.z, bb.w};
#pragma unroll
    for (int si = 0; si < 4; ++si) {
        int n = n0 + w * 4 + si;
#pragma unroll
        for (int jj = 0; jj < 4; ++jj) {
            float val = acc[si][jj] + bvv[jj];
            if (ct < 12) {
                int j = ct * 128 + l * 4 + jj;
                if (j < 1024) val += b_hh[j];     // fold b_hh into r,z gates
                g_gctx[(size_t)n * G3 + j] = val;
            } else {
                g_fcctx[(size_t)n * VV + l * 4 + jj] = val;
            }
        }
    }
}

// ---------------- persistent decode kernel internals ----------------
__device__ __forceinline__ void copy_chunk(uint32_t smb, int buf, const __nv_bfloat16* src, int t) {
    uint32_t dbase = smb + SM_B + buf * B_BUF;
    const char* s = (const char*)src;
#pragma unroll
    for (int i = 0; i < 8; ++i) {
        int u = t + i * 256;
        int sp = u >> 10, rem = u & 1023, n = rem >> 3, c = rem & 7;
        cp16(dbase + sp * B_SPL + n * 144 + c * 16, s + sp * 16384 + n * 128 + c * 16);
    }
}

__device__ __forceinline__ void mma_chunk(uint32_t smb, int buf, int kc,
                                          int wy, int wx, int lane, float* acc) {
    uint32_t abase = smb + SM_A;
    uint32_t bbase = smb + SM_B + buf * B_BUF;
    int arow = wy * 32 + (lane & 7) + ((lane >> 3) & 1) * 8;
    int akoff = ((lane >> 4) & 1) * 8;
    int brow = wx * 32 + ((lane >> 4) & 1) * 8 + (lane & 7);
    int bkoff = ((lane >> 3) & 1) * 8;
#pragma unroll
    for (int ks = 0; ks < 4; ++ks) {
        int kA = kc * 64 + ks * 16 + akoff;
        uint32_t ahi[2][4], alo[2][4];
#pragma unroll
        for (int mt = 0; mt < 2; ++mt) {
            uint32_t ad = abase + ((arow + mt * 16) * 520 + kA) * 2;
            ldsm4(ad, ahi[mt]);
            ldsm4(ad + A_SPLIT, alo[mt]);
        }
        uint32_t bhi[4][2], blo[4][2];
#pragma unroll
        for (int p = 0; p < 2; ++p) {
            uint32_t bd = bbase + ((brow + p * 16) * 72 + ks * 16 + bkoff) * 2;
            uint32_t r4[4];
            ldsm4(bd, r4);
            bhi[2 * p][0] = r4[0]; bhi[2 * p][1] = r4[1];
            bhi[2 * p + 1][0] = r4[2]; bhi[2 * p + 1][1] = r4[3];
            ldsm4(bd + B_SPL, r4);
            blo[2 * p][0] = r4[0]; blo[2 * p][1] = r4[1];
            blo[2 * p + 1][0] = r4[2]; blo[2 * p + 1][1] = r4[3];
        }
#pragma unroll
        for (int mt = 0; mt < 2; ++mt)
#pragma unroll
            for (int nt = 0; nt < 4; ++nt) {
                float* c = acc + (mt * 4 + nt) * 4;
                mma16816(c, ahi[mt], bhi[nt]);
                mma16816(c, ahi[mt], blo[nt]);
                mma16816(c, alo[mt], bhi[nt]);
            }
    }
}

__device__ __forceinline__ void compute_tile(const __nv_bfloat16* Bsrc, float* acc,
                                             uint32_t smb, int wy, int wx, int lane, int t) {
#pragma unroll
    for (int i = 0; i < 32; ++i) acc[i] = 0.f;
    copy_chunk(smb, 0, Bsrc, t);
    asm volatile("cp.async.commit_group;" ::: "memory");
#pragma unroll 1
    for (int kc = 0; kc < 8; ++kc) {
        if (kc < 7) {
            copy_chunk(smb, (kc + 1) & 1, Bsrc + (size_t)(kc + 1) * 16384, t);
            asm volatile("cp.async.commit_group;" ::: "memory");
            asm volatile("cp.async.wait_group 1;" ::: "memory");
        } else {
            asm volatile("cp.async.wait_group 0;" ::: "memory");
        }
        __syncthreads();
        mma_chunk(smb, kc & 1, kc, wy, wx, lane, acc);
        __syncthreads();
    }
}

__device__ __forceinline__ void packA(char* sm, const float* __restrict__ src, int t) {
#pragma unroll 4
    for (int i = 0; i < 32; ++i) {
        int idx = t + i * 256;                 // 8192 float4
        int r = idx >> 7, kq = (idx & 127) * 4;
        float4 v = *(const float4*)(src + (size_t)r * HHD + kq);
        unsigned short h0, l0, h1, l1, h2, l2, h3, l3;
        bsplit(v.x, h0, l0); bsplit(v.y, h1, l1);
        bsplit(v.z, h2, l2); bsplit(v.w, h3, l3);
        char* d = sm + SM_A + (r * 520 + kq) * 2;
        *(uint32_t*)d = (uint32_t)h0 | ((uint32_t)h1 << 16);
        *(uint32_t*)(d + 4) = (uint32_t)h2 | ((uint32_t)h3 << 16);
        *(uint32_t*)(d + A_SPLIT) = (uint32_t)l0 | ((uint32_t)l1 << 16);
        *(uint32_t*)(d + A_SPLIT + 4) = (uint32_t)l2 | ((uint32_t)l3 << 16);
    }
}

__global__ __launch_bounds__(256, 1)
void decode_kernel(const float* __restrict__ encoded, const int* __restrict__ init_char,
                   const float* __restrict__ b_hh, float* __restrict__ out) {
    extern __shared__ char smraw[];
    char* sm = smraw;
    uint32_t smb = smem_u32(sm);
    const int t = threadIdx.x, lane = t & 31, warp = t >> 5;
    const int wy = warp >> 2, wx = warp & 3;
    const int cta = blockIdx.x;
    int* sch = (int*)(sm + SM_SCH);
    float* sbhn = (float*)(sm + SM_BHN);
    float* sargv = (float*)(sm + SM_ARGV);
    int* sargi = (int*)(sm + SM_ARGI);

    for (int i = t; i < 512; i += 256) sbhn[i] = b_hh[1024 + i];
    if (t < CROWS) sch[t] = init_char[cta * CROWS + t];
    packA(sm, encoded + (size_t)cta * CROWS * HHD, t);
    __syncthreads();

    for (int step = 0; step < SSTEPS; ++step) {
        float str[32], stz[32], acc[32];
#pragma unroll 1
        for (int jt = 0; jt < 4; ++jt) {
            compute_tile(g_wpack + (size_t)(jt * 3 + 0) * 8 * 16384, str, smb, wy, wx, lane, t);
            compute_tile(g_wpack + (size_t)(jt * 3 + 1) * 8 * 16384, stz, smb, wy, wx, lane, t);
            compute_tile(g_wpack + (size_t)(jt * 3 + 2) * 8 * 16384, acc, smb, wy, wx, lane, t);
            // ---- gate epilogue for this j-tile ----
#pragma unroll
            for (int mt = 0; mt < 2; ++mt)
#pragma unroll
                for (int nt = 0; nt < 4; ++nt)
#pragma unroll
                    for (int hh = 0; hh < 2; ++hh) {
                        int row = wy * 32 + mt * 16 + (lane >> 2) + hh * 8;
                        int jcol = jt * 128 + wx * 32 + nt * 8 + (lane & 3) * 2;
                        int ng = cta * CROWS + row;
                        int cc = sch[row];
                        const float* gp = g_gctx + (size_t)ng * G3 + jcol;
                        const float* ep = g_embgi + (size_t)cc * G3 + jcol;
                        float2 gr = *(const float2*)gp;
                        float2 gz = *(const float2*)(gp + 512);
                        float2 gn = *(const float2*)(gp + 1024);
                        float2 er = *(const float2*)ep;
                        float2 ez = *(const float2*)(ep + 512);
                        float2 en = *(const float2*)(ep + 1024);
                        // old h from packed A
                        const char* ha = sm + SM_A + (row * 520 + jcol) * 2;
                        __nv_bfloat162 hv = *(const __nv_bfloat162*)ha;
                        __nv_bfloat162 lv = *(const __nv_bfloat162*)(ha + A_SPLIT);
                        float ho0 = __bfloat162float(hv.x) + __bfloat162float(lv.x);
                        float ho1 = __bfloat162float(hv.y) + __bfloat162float(lv.y);
                        int base = (mt * 4 + nt) * 4 + hh * 2;
                        float pr0 = gr.x + er.x + str[base];
                        float pr1 = gr.y + er.y + str[base + 1];
                        float pz0 = gz.x + ez.x + stz[base];
                        float pz1 = gz.y + ez.y + stz[base + 1];
                        float hn0 = acc[base] + sbhn[jcol];
                        float hn1 = acc[base + 1] + sbhn[jcol + 1];
                        float r0 = 1.f / (1.f + expf(-pr0));
                        float r1 = 1.f / (1.f + expf(-pr1));
                        float z0 = 1.f / (1.f + expf(-pz0));
                        float z1 = 1.f / (1.f + expf(-pz1));
                        float n0 = tanhf(gn.x + en.x + r0 * hn0);
                        float n1 = tanhf(gn.y + en.y + r1 * hn1);
                        float2 hnew;
                        hnew.x = (1.f - z0) * n0 + z0 * ho0;
                        hnew.y = (1.f - z1) * n1 + z1 * ho1;
                        *(float2*)(g_h + (size_t)ng * HHD + jcol) = hnew;
                    }
        }
        __syncthreads();                       // g_h writes visible; A reads done
        packA(sm, g_h + (size_t)cta * CROWS * HHD, t);   // A <- h_new
        __syncthreads();

        // ---- fc GEMM ----
        compute_tile(g_fcpack, acc, smb, wy, wx, lane, t);

        // ---- fc epilogue: logits, out, argmax ----
        float best[4]; int bidx[4];
#pragma unroll
        for (int s = 0; s < 4; ++s) { best[s] = -1e30f; bidx[s] = 0; }
#pragma unroll
        for (int mt = 0; mt < 2; ++mt)
#pragma unroll
            for (int hh = 0; hh < 2; ++hh) {
                int slot = mt * 2 + hh;
                int row = wy * 32 + mt * 16 + (lane >> 2) + hh * 8;
                int ng = cta * CROWS + row;
                int cc = sch[row];
#pragma unroll
                for (int nt = 0; nt < 4; ++nt) {
                    int v = wx * 32 + nt * 8 + (lane & 3) * 2;
                    int base = (mt * 4 + nt) * 4 + hh * 2;
                    float2 fc = *(const float2*)(g_fcctx + (size_t)ng * VV + v);
                    float2 fe = *(const float2*)(g_fcemb + (size_t)cc * VV + v);
                    float p0 = acc[base] + fc.x + fe.x;
                    float p1 = acc[base + 1] + fc.y + fe.y;
                    float2 pv; pv.x = p0; pv.y = p1;
                    *(float2*)(out + ((size_t)ng * SSTEPS + step) * VV + v) = pv;
                    if (p0 > best[slot]) { best[slot] = p0; bidx[slot] = v; }
                    if (p1 > best[slot]) { best[slot] = p1; bidx[slot] = v + 1; }
                }
            }
        // quad reduce (lanes sharing lane>>2 hold the same rows)
#pragma unroll
        for (int s = 0; s < 4; ++s) {
#pragma unroll
            for (int off = 1; off <= 2; off <<= 1) {
                float ov = __shfl_xor_sync(0xffffffffu, best[s], off);
                int oi = __shfl_xor_sync(0xffffffffu, bidx[s], off);
                if (ov > best[s] || (ov == best[s] && oi < bidx[s])) { best[s] = ov; bidx[s] = oi; }
            }
        }
        if ((lane & 3) == 0) {
#pragma unroll
            for (int s = 0; s < 4; ++s) {
                int row = wy * 32 + (s >> 1) * 16 + (lane >> 2) + (s & 1) * 8;
                sargv[row * 4 + wx] = best[s];
                sargi[row * 4 + wx] = bidx[s];
            }
        }
        __syncthreads();
        if (t < CROWS) {
            float bv = sargv[t * 4]; int bi = sargi[t * 4];
#pragma unroll
            for (int wxi = 1; wxi < 4; ++wxi) {
                float ov = sargv[t * 4 + wxi]; int oi = sargi[t * 4 + wxi];
                if (ov > bv || (ov == bv && oi < bi)) { bv = ov; bi = oi; }
            }
            sch[t] = bi;
        }
        __syncthreads();
    }
}

// ---------------------------------------------------------------------------
extern "C" void kernel_launch(void* const* d_in, const int* in_sizes, int n_in,
                              void* d_out, int out_size) {
    const float *encoded = 0, *emb_table = 0, *W_ih = 0, *W_hh = 0,
                *b_ih = 0, *b_hh = 0, *fc_W = 0, *fc_b = 0;
    const int* init_char = 0;
    for (int i = 0; i < n_in; ++i) {
        switch (in_sizes[i]) {
            case 8192 * 512:  encoded   = (const float*)d_in[i]; break;
            case 8192:        init_char = (const int*)d_in[i];   break;
            case 128 * 128:   emb_table = (const float*)d_in[i]; break;
            case 1536 * 640:  W_ih      = (const float*)d_in[i]; break;
            case 1536 * 512:  W_hh      = (const float*)d_in[i]; break;
            case 1536:        if (!b_ih) b_ih = (const float*)d_in[i];
                              else       b_hh = (const float*)d_in[i]; break;
            case 128 * 1152:  fc_W      = (const float*)d_in[i]; break;
            case 128:         fc_b      = (const float*)d_in[i]; break;
            default: break;
        }
    }
    float* out = (float*)d_out;

    cudaFuncSetAttribute(ctx_kernel, cudaFuncAttributeMaxDynamicSharedMemorySize,
                         (HHD * 32 + 16 * 128) * (int)sizeof(float));
    cudaFuncSetAttribute(decode_kernel, cudaFuncAttributeMaxDynamicSharedMemorySize,
                         SMEM_TOT);

    pack_w_kernel<<<(G3 * HHD + 255) / 256, 256>>>(W_hh);
    pack_fc_kernel<<<(VV * HHD + 255) / 256, 256>>>(fc_W);
    emb_kernel<<<dim3(13, 128), 128>>>(emb_table, W_ih, fc_W);
    ctx_kernel<<<dim3(256, 13), 256, (HHD * 32 + 16 * 128) * sizeof(float)>>>(
        encoded, W_ih, b_ih, b_hh, fc_W, fc_b);
    decode_kernel<<<NCTA, 256, SMEM_TOT>>>(encoded, init_char, b_hh, out);
}